// round 16
// baseline (speedup 1.0000x reference)
#include <cuda_runtime.h>
#include <math.h>
#include <stdint.h>

// Problem constants (fixed shapes)
#define BB   2
#define NN   512
#define DIMV 384
#define TOK  (BB*NN)          // 1024

#define SCALAR_SCALE 0.14433756729740643f   // (3*16)^-0.5
#define POINT_SCALE  0.13608276348795434f   // (3*4*4.5)^-0.5
#define PAIR_SCALE   0.57735026918962576f   // 3^-0.5
#define EPSV 1e-8f

// attention tiling
#define IT 4      // queries per block
#define JT 32     // keys per tile

#define KSPLIT 4

// ---------------- device scratch ----------------
__device__ float g_q[TOK*224];
__device__ float g_kv[TOK*448];
__device__ float g_qsq[TOK*8];
__device__ float g_ksq[TOK*8];
__device__ float g_feats[TOK*1280];
__device__ float g_part[KSPLIT*TOK*DIMV];
__device__ float g_bias[(size_t)TOK*NN*8];   // [bi][j][h], 16 MB

// =====================================================================
// Standalone pair-bias GEMM: bias[bi][j][h] = PAIR_SCALE*(pair[bi,j]·w_pair[:,h] + b_pair[h])
// grid 4096 (128 rows/block), 256 threads (2 per row). DRAM-bound.
// =====================================================================
__global__ __launch_bounds__(256) void pair_bias_kernel(
    const float* __restrict__ pairwise,
    const float* __restrict__ w_pair,
    const float* __restrict__ b_pair,
    float* __restrict__ bias_out)
{
    __shared__ __align__(16) float wpm[1024];   // [p][h] pre-scaled
    __shared__ float bp[8];
    __shared__ __align__(16) float pb[2048];    // partials [rl*2+ph][h]
    const int tid = threadIdx.x;
#pragma unroll
    for (int l = 0; l < 4; ++l) wpm[l*256 + tid] = w_pair[l*256 + tid] * PAIR_SCALE;
    if (tid < 8) bp[tid] = b_pair[tid] * PAIR_SCALE;
    __syncthreads();

    const int rl = tid >> 1, ph = tid & 1;
    const float* src = pairwise + ((size_t)blockIdx.x*128 + rl)*128 + ph*64;
    float acc[8];
#pragma unroll
    for (int h = 0; h < 8; ++h) acc[h] = 0.f;
#pragma unroll
    for (int i = 0; i < 16; ++i) {
        float4 pv = *(const float4*)(src + i*4);
        const float* wp = &wpm[(ph*64 + i*4)*8];
        float pe[4] = { pv.x, pv.y, pv.z, pv.w };
#pragma unroll
        for (int e = 0; e < 4; ++e) {
            float4 wa = *(const float4*)(wp + e*8);
            float4 wb = *(const float4*)(wp + e*8 + 4);
            acc[0] += pe[e]*wa.x; acc[1] += pe[e]*wa.y;
            acc[2] += pe[e]*wa.z; acc[3] += pe[e]*wa.w;
            acc[4] += pe[e]*wb.x; acc[5] += pe[e]*wb.y;
            acc[6] += pe[e]*wb.z; acc[7] += pe[e]*wb.w;
        }
    }
    float* pbp = &pb[tid*8];
#pragma unroll
    for (int h = 0; h < 8; ++h) pbp[h] = acc[h];
    __syncthreads();
#pragma unroll
    for (int k = 0; k < 4; ++k) {
        int o = tid*4 + k;                 // 1024 outputs: row*8 + h
        int row = o >> 3, h = o & 7;
        bias_out[((size_t)blockIdx.x*128 + row)*8 + h] =
            pb[(row*2)*8 + h] + pb[(row*2+1)*8 + h] + bp[h];
    }
}

// =====================================================================
// Fused projection GEMM: all 6 projections in one launch.
// =====================================================================
__global__ __launch_bounds__(256) void proj_fused_kernel(
    const float* __restrict__ q_in, const float* __restrict__ kv_in,
    const float* __restrict__ w_sq, const float* __restrict__ w_pq,
    const float* __restrict__ w_sk, const float* __restrict__ w_sv,
    const float* __restrict__ w_pk, const float* __restrict__ w_pv,
    float* __restrict__ Cq, float* __restrict__ Ckv)
{
    __shared__ __align__(16) float As[16][68];
    __shared__ __align__(16) float Ws[16][32];

    const int tid  = threadIdx.x;
    const int row0 = blockIdx.y * 64;
    const int col0 = blockIdx.x * 32;

    const float* A; const float* W; int nseg, wcol;
    float* C; int Ctot, ccol;
    if (col0 < 128)      { A=q_in;  W=w_sq; nseg=128; wcol=col0;     C=Cq;  Ctot=224; ccol=col0; }
    else if (col0 < 224) { A=q_in;  W=w_pq; nseg=96;  wcol=col0-128; C=Cq;  Ctot=224; ccol=col0; }
    else if (col0 < 352) { A=kv_in; W=w_sk; nseg=128; wcol=col0-224; C=Ckv; Ctot=448; ccol=col0-224; }
    else if (col0 < 480) { A=kv_in; W=w_sv; nseg=128; wcol=col0-352; C=Ckv; Ctot=448; ccol=col0-224; }
    else if (col0 < 576) { A=kv_in; W=w_pk; nseg=96;  wcol=col0-480; C=Ckv; Ctot=448; ccol=col0-224; }
    else                 { A=kv_in; W=w_pv; nseg=96;  wcol=col0-576; C=Ckv; Ctot=448; ccol=col0-224; }

    const int my = tid >> 4;
    const int nx = tid & 15;

    float acc[4][2];
#pragma unroll
    for (int i = 0; i < 4; ++i) { acc[i][0] = 0.f; acc[i][1] = 0.f; }

    const int lr = tid >> 2;
    const int lk = (tid & 3) * 4;

    for (int k0 = 0; k0 < DIMV; k0 += 16) {
        float4 av = *(const float4*)(A + (size_t)(row0 + lr)*DIMV + k0 + lk);
        As[lk+0][lr] = av.x; As[lk+1][lr] = av.y;
        As[lk+2][lr] = av.z; As[lk+3][lr] = av.w;
        if (tid < 128) {
            int wk = tid >> 3, wn = (tid & 7) * 4;
            *(float4*)&Ws[wk][wn] = *(const float4*)(W + (size_t)(k0 + wk)*nseg + wcol + wn);
        }
        __syncthreads();
#pragma unroll
        for (int kk = 0; kk < 16; ++kk) {
            float4 a = *(const float4*)&As[kk][my*4];
            float2 w = *(const float2*)&Ws[kk][nx*2];
            acc[0][0] += a.x*w.x; acc[0][1] += a.x*w.y;
            acc[1][0] += a.y*w.x; acc[1][1] += a.y*w.y;
            acc[2][0] += a.z*w.x; acc[2][1] += a.z*w.y;
            acc[3][0] += a.w*w.x; acc[3][1] += a.w*w.y;
        }
        __syncthreads();
    }
#pragma unroll
    for (int i = 0; i < 4; ++i) {
        float* cr = C + (size_t)(row0 + my*4 + i)*Ctot + ccol + nx*2;
        cr[0] = acc[i][0]; cr[1] = acc[i][1];
    }
}

// =====================================================================
// Output GEMM, 64x64 tile, 4x4 per thread, K split in 4 via blockIdx.z.
// =====================================================================
__global__ __launch_bounds__(256) void out_gemm_part(
    const float* __restrict__ A, const float* __restrict__ W,
    float* __restrict__ P)
{
    __shared__ __align__(16) float As[16][68];
    __shared__ __align__(16) float Ws[16][68];

    const int tid  = threadIdx.x;
    const int row0 = blockIdx.y * 64;
    const int col0 = blockIdx.x * 64;
    const int kh   = blockIdx.z;
    const int my = tid >> 4;
    const int nx = tid & 15;

    float acc[4][4];
#pragma unroll
    for (int i = 0; i < 4; ++i)
#pragma unroll
        for (int j = 0; j < 4; ++j) acc[i][j] = 0.f;

    const int lr = tid >> 2;
    const int lk = (tid & 3) * 4;
    const int wk = tid >> 4;
    const int wn = (tid & 15) * 4;

    const int kbeg = kh * 320, kend = kbeg + 320;

    for (int k0 = kbeg; k0 < kend; k0 += 16) {
        float4 av = *(const float4*)(A + (size_t)(row0 + lr)*1280 + k0 + lk);
        As[lk+0][lr] = av.x; As[lk+1][lr] = av.y;
        As[lk+2][lr] = av.z; As[lk+3][lr] = av.w;
        *(float4*)&Ws[wk][wn] = *(const float4*)(W + (size_t)(k0 + wk)*DIMV + col0 + wn);
        __syncthreads();
#pragma unroll
        for (int kk = 0; kk < 16; ++kk) {
            float4 a = *(const float4*)&As[kk][my*4];
            float4 w = *(const float4*)&Ws[kk][nx*4];
            acc[0][0] += a.x*w.x; acc[0][1] += a.x*w.y; acc[0][2] += a.x*w.z; acc[0][3] += a.x*w.w;
            acc[1][0] += a.y*w.x; acc[1][1] += a.y*w.y; acc[1][2] += a.y*w.z; acc[1][3] += a.y*w.w;
            acc[2][0] += a.z*w.x; acc[2][1] += a.z*w.y; acc[2][2] += a.z*w.z; acc[2][3] += a.z*w.w;
            acc[3][0] += a.w*w.x; acc[3][1] += a.w*w.y; acc[3][2] += a.w*w.z; acc[3][3] += a.w*w.w;
        }
        __syncthreads();
    }
    float* dst = P + (size_t)kh*TOK*DIMV;
#pragma unroll
    for (int i = 0; i < 4; ++i) {
        float* cr = dst + (size_t)(row0 + my*4 + i)*DIMV + col0 + nx*4;
        cr[0] = acc[i][0]; cr[1] = acc[i][1]; cr[2] = acc[i][2]; cr[3] = acc[i][3];
    }
}

__global__ __launch_bounds__(256) void add_bias_kernel(
    const float* __restrict__ bias, float* __restrict__ out)
{
    int idx = blockIdx.x * 256 + threadIdx.x;
    const int S = TOK*DIMV;
    float r = bias[idx % DIMV];
#pragma unroll
    for (int k = 0; k < KSPLIT; ++k) r += g_part[(size_t)k*S + idx];
    out[idx] = r;
}

// ---------------- rotate kernels ----------------
__global__ void rotate_q_kernel(const float* __restrict__ rot,
                                const float* __restrict__ trans)
{
    const int bn  = blockIdx.x;
    const int tid = threadIdx.x;   // 32
    float r[9], t3[3];
#pragma unroll
    for (int k = 0; k < 9; ++k) r[k] = rot[bn*9 + k];
#pragma unroll
    for (int k = 0; k < 3; ++k) t3[k] = trans[bn*3 + k];
    float* base = g_q + (size_t)bn*224 + 128 + tid*3;
    float c0 = base[0], c1 = base[1], c2 = base[2];
    float o0 = c0*r[0] + c1*r[3] + c2*r[6] + t3[0];
    float o1 = c0*r[1] + c1*r[4] + c2*r[7] + t3[1];
    float o2 = c0*r[2] + c1*r[5] + c2*r[8] + t3[2];
    base[0] = o0; base[1] = o1; base[2] = o2;
    float sq = o0*o0 + o1*o1 + o2*o2;
#pragma unroll
    for (int off = 1; off < 4; off <<= 1)
        sq += __shfl_xor_sync(0xffffffffu, sq, off);
    if ((tid & 3) == 0) g_qsq[bn*8 + (tid >> 2)] = sq;
}

__global__ void rotate_kv_kernel(const float* __restrict__ rot,
                                 const float* __restrict__ trans)
{
    const int bn  = blockIdx.x;
    const int tid = threadIdx.x;   // 32
    float r[9], t3[3];
#pragma unroll
    for (int k = 0; k < 9; ++k) r[k] = rot[bn*9 + k];
#pragma unroll
    for (int k = 0; k < 3; ++k) t3[k] = trans[bn*3 + k];
    float* arrs[2] = { g_kv + (size_t)bn*448 + 256,    // kp
                       g_kv + (size_t)bn*448 + 352 };  // vp
    float sq = 0.f;
#pragma unroll
    for (int a = 0; a < 2; ++a) {
        float* base = arrs[a] + tid*3;
        float c0 = base[0], c1 = base[1], c2 = base[2];
        float o0 = c0*r[0] + c1*r[3] + c2*r[6] + t3[0];
        float o1 = c0*r[1] + c1*r[4] + c2*r[7] + t3[1];
        float o2 = c0*r[2] + c1*r[5] + c2*r[8] + t3[2];
        base[0] = o0; base[1] = o1; base[2] = o2;
        if (a == 0) sq = o0*o0 + o1*o1 + o2*o2;
    }
#pragma unroll
    for (int off = 1; off < 4; off <<= 1)
        sq += __shfl_xor_sync(0xffffffffu, sq, off);
    if ((tid & 3) == 0) g_ksq[bn*8 + (tid >> 2)] = sq;
}

// =====================================================================
// Fused attention (phase A extracted; Z on all threads, warp = head).
// grid = 256, 256 threads, smem ~77KB, 2 blocks/SM.
// =====================================================================
// smem float offsets
#define OF_PAIR  0                      // 128 rows x 128 (swizzled)
#define OF_WEXP  16384                  // [ii][h][jj] 4*8*32
#define OF_QS    17408                  // [ii][128]
#define OF_QP    17920                  // [ii][96]
#define OF_QSQ   18304                  // [ii][8]
#define OF_M     18336
#define OF_L     18368
#define OF_ALPHA 18400
#define OF_COEF  18432                  // [8]
#define OF_R     18440                  // [ii][9]
#define OF_T     18476                  // [ii][3]
#define OF_PTS   18488                  // [ii][96]
#define OF_PTSL  18872                  // [ii][96]
#define SM_FLOATS 19256
#define SM_BYTES (SM_FLOATS*4)

__global__ __launch_bounds__(256, 2) void ipa_attn_kernel(
    const float* __restrict__ pairwise,
    const float* __restrict__ rot,
    const float* __restrict__ trans,
    const float* __restrict__ point_w)
{
    extern __shared__ __align__(16) float sm[];
    float* pairT = sm + OF_PAIR;
    float* wexp  = sm + OF_WEXP;
    float* qs_s  = sm + OF_QS;
    float* qp_s  = sm + OF_QP;
    float* qsq_s = sm + OF_QSQ;
    float* m_s   = sm + OF_M;
    float* l_s   = sm + OF_L;
    float* al_s  = sm + OF_ALPHA;
    float* cf_s  = sm + OF_COEF;
    float* R_s   = sm + OF_R;
    float* T_s   = sm + OF_T;
    float* pts_s = sm + OF_PTS;
    float* ptl_s = sm + OF_PTSL;

    const int tid  = threadIdx.x;
    const int bid  = blockIdx.x;
    const int b    = bid >> 7;
    const int i0   = (bid & 127) * IT;
    const int w    = tid >> 5;
    const int lane = tid & 31;

    // ---- prologue loads ----
#pragma unroll
    for (int l = 0; l < 2; ++l) {             // qs: 512 floats
        int idx = l*256 + tid;
        int ii = idx >> 7;
        qs_s[idx] = g_q[(size_t)(b*NN + i0 + ii)*224 + (idx & 127)];
    }
#pragma unroll
    for (int idx = tid; idx < IT*96; idx += 256) {   // qp: 384 floats
        int ii = idx / 96;
        qp_s[idx] = g_q[(size_t)(b*NN + i0 + ii)*224 + 128 + (idx % 96)];
    }
    if (tid < 32) {
        int ii = tid >> 3;
        qsq_s[tid] = g_qsq[(size_t)(b*NN + i0 + ii)*8 + (tid & 7)];
        m_s[tid] = -1e30f;
        l_s[tid] = 0.f;
    }
    if (tid < 8) {
        float x = point_w[tid];
        cf_s[tid] = -0.5f * POINT_SCALE * log1pf(__expf(x));
    }
    if (tid >= 64 && tid < 100) {             // R: 36
        int idx = tid - 64;
        int ii = idx / 9;
        R_s[idx] = rot[(size_t)(b*NN + i0 + ii)*9 + (idx % 9)];
    }
    if (tid >= 100 && tid < 112) {            // T: 12
        int idx = tid - 100;
        int ii = idx / 3;
        T_s[idx] = trans[(size_t)(b*NN + i0 + ii)*3 + (idx % 3)];
    }
    __syncthreads();

    // persistent accumulators
    float4 aH[8];                             // res_pair (warps 0-3): warp=ii, 8 heads
#pragma unroll
    for (int h = 0; h < 8; ++h) aH[h] = make_float4(0,0,0,0);
    float accs[IT] = {0,0,0,0}, accp[IT] = {0,0,0,0};   // value (warps 4-7)
    const int tv = tid - 128;
    const int hs = (tv >= 0) ? (tv >> 4) : 0;
    const int fs = (tv >= 0) ? (tv & 15) : 0;
    const bool vp_act = (tv >= 0) && (tv < 96);
    const int hp = vp_act ? (tv / 12) : 0;
    const int fp = vp_act ? (tv % 12) : 0;

    const float* gp_base = pairwise + ((size_t)b*NN + i0) * NN * 128;
    const int lane4 = lane << 2;
    const float cfw = cf_s[w];

    for (int tile = 0; tile < 16; ++tile) {
        const int j0 = tile * JT;
        // ---- load pair tiles: 4 ii x 32 jj x 128 p (XOR swizzled quads) ----
        {
#pragma unroll
            for (int l = 0; l < 16; ++l) {
                int idx = l*256 + tid;
                int ii  = idx >> 10;
                int rem = idx & 1023;
                int jj  = rem >> 5;
                int q   = rem & 31;
                int physq = q ^ (jj & 7);
                *(float4*)&pairT[((ii*JT + jj) << 7) + (physq << 2)] =
                    *(const float4*)(gp_base + ((size_t)ii*NN + j0 + jj)*128 + (q << 2));
            }
        }
        __syncthreads();

        // ---- phase Z: all 256 threads; warp = head, lane = jj ----
        {
            const int jz = j0 + lane;
            const size_t bj = (size_t)b*NN + jz;
            const float* kvr = g_kv + bj*448;
            float4 kf0 = *(const float4*)(kvr + w*16);
            float4 kf1 = *(const float4*)(kvr + w*16 + 4);
            float4 kf2 = *(const float4*)(kvr + w*16 + 8);
            float4 kf3 = *(const float4*)(kvr + w*16 + 12);
            float4 kp0 = *(const float4*)(kvr + 256 + w*12);
            float4 kp1 = *(const float4*)(kvr + 256 + w*12 + 4);
            float4 kp2 = *(const float4*)(kvr + 256 + w*12 + 8);
            float kq = g_ksq[bj*8 + w];
#pragma unroll
            for (int ii = 0; ii < IT; ++ii) {
                float bz = g_bias[(((size_t)(b*NN + i0 + ii))*NN + jz)*8 + w];
                const float* qsr = qs_s + ii*128 + w*16;   // warp-uniform
                const float* qpr = qp_s + ii*96 + w*12;
                float4 q0 = *(const float4*)(qsr);
                float4 q1 = *(const float4*)(qsr + 4);
                float4 q2 = *(const float4*)(qsr + 8);
                float4 q3 = *(const float4*)(qsr + 12);
                float s = q0.x*kf0.x + q0.y*kf0.y + q0.z*kf0.z + q0.w*kf0.w
                        + q1.x*kf1.x + q1.y*kf1.y + q1.z*kf1.z + q1.w*kf1.w
                        + q2.x*kf2.x + q2.y*kf2.y + q2.z*kf2.z + q2.w*kf2.w
                        + q3.x*kf3.x + q3.y*kf3.y + q3.z*kf3.z + q3.w*kf3.w;
                float4 p0 = *(const float4*)(qpr);
                float4 p1 = *(const float4*)(qpr + 4);
                float4 p2 = *(const float4*)(qpr + 8);
                float dt = p0.x*kp0.x + p0.y*kp0.y + p0.z*kp0.z + p0.w*kp0.w
                         + p1.x*kp1.x + p1.y*kp1.y + p1.z*kp1.z + p1.w*kp1.w
                         + p2.x*kp2.x + p2.y*kp2.y + p2.z*kp2.z + p2.w*kp2.w;
                float dist = qsq_s[ii*8 + w] + kq - 2.f*dt;
                wexp[ii*256 + w*32 + lane] = s*SCALAR_SCALE + bz + cfw*dist;
            }
        }
        __syncthreads();

        // ---- phase C: online softmax (warp w owns head w) ----
        {
#pragma unroll
            for (int ii = 0; ii < IT; ++ii) {
                float v = wexp[ii*256 + w*32 + lane];
                float mx = v;
#pragma unroll
                for (int off = 16; off; off >>= 1)
                    mx = fmaxf(mx, __shfl_xor_sync(0xffffffffu, mx, off));
                float mold = m_s[ii*8 + w];
                float mnew = fmaxf(mold, mx);
                float a = __expf(mold - mnew);
                float e = __expf(v - mnew);
                wexp[ii*256 + w*32 + lane] = e;
                float smv = e;
#pragma unroll
                for (int off = 16; off; off >>= 1)
                    smv += __shfl_xor_sync(0xffffffffu, smv, off);
                if (lane == 0) {
                    l_s[ii*8 + w] = l_s[ii*8 + w]*a + smv;
                    m_s[ii*8 + w] = mnew;
                    al_s[ii*8 + w] = a;
                }
            }
        }
        __syncthreads();

        // ---- phase D ----
        if (tid < 128) {
            // res_pair: warp w owns QUERY ii=w, all 8 heads; lane owns p-quad.
            const int iiw = w;
#pragma unroll
            for (int h = 0; h < 8; ++h) {
                float sA = al_s[iiw*8 + h];
                aH[h].x *= sA; aH[h].y *= sA; aH[h].z *= sA; aH[h].w *= sA;
            }
            const float* we = &wexp[iiw*256];
            const float* tb = &pairT[(iiw*JT) << 7];
#pragma unroll
            for (int jj = 0; jj < JT; jj += 4) {
                float4 r0 = *(const float4*)(tb + ((jj+0)<<7) + (lane4 ^ (((jj+0)&7)<<2)));
                float4 r1 = *(const float4*)(tb + ((jj+1)<<7) + (lane4 ^ (((jj+1)&7)<<2)));
                float4 r2 = *(const float4*)(tb + ((jj+2)<<7) + (lane4 ^ (((jj+2)&7)<<2)));
                float4 r3 = *(const float4*)(tb + ((jj+3)<<7) + (lane4 ^ (((jj+3)&7)<<2)));
#pragma unroll
                for (int h = 0; h < 8; ++h) {
                    float4 wA = *(const float4*)(we + h*32 + jj);   // broadcast
                    aH[h].x += wA.x*r0.x + wA.y*r1.x + wA.z*r2.x + wA.w*r3.x;
                    aH[h].y += wA.x*r0.y + wA.y*r1.y + wA.z*r2.y + wA.w*r3.y;
                    aH[h].z += wA.x*r0.z + wA.y*r1.z + wA.z*r2.z + wA.w*r3.z;
                    aH[h].w += wA.x*r0.w + wA.y*r1.w + wA.z*r2.w + wA.w*r3.w;
                }
            }
        } else {
            // values: scalar feats (all 128) + point feats (first 96)
#pragma unroll
            for (int ii = 0; ii < IT; ++ii) {
                accs[ii] *= al_s[ii*8 + hs];
                if (vp_act) accp[ii] *= al_s[ii*8 + hp];
            }
            const float* vbase = g_kv + ((size_t)b*NN + j0)*448;
            const float* svs = vbase + 128 + hs*16 + fs;
            const float* svp = vbase + 352 + hp*12 + fp;
#pragma unroll
            for (int jj4 = 0; jj4 < JT; jj4 += 4) {
                float v0 = svs[(size_t)(jj4+0)*448];
                float v1 = svs[(size_t)(jj4+1)*448];
                float v2 = svs[(size_t)(jj4+2)*448];
                float v3 = svs[(size_t)(jj4+3)*448];
#pragma unroll
                for (int ii = 0; ii < IT; ++ii) {
                    float4 w4 = *(const float4*)&wexp[ii*256 + hs*32 + jj4];
                    accs[ii] += w4.x*v0 + w4.y*v1 + w4.z*v2 + w4.w*v3;
                }
                if (vp_act) {
                    float u0 = svp[(size_t)(jj4+0)*448];
                    float u1 = svp[(size_t)(jj4+1)*448];
                    float u2 = svp[(size_t)(jj4+2)*448];
                    float u3 = svp[(size_t)(jj4+3)*448];
#pragma unroll
                    for (int ii = 0; ii < IT; ++ii) {
                        float4 w4 = *(const float4*)&wexp[ii*256 + hp*32 + jj4];
                        accp[ii] += w4.x*u0 + w4.y*u1 + w4.z*u2 + w4.w*u3;
                    }
                }
            }
        }
        __syncthreads();
    }

    // ---- finalize ----
    if (tid < 128) {
        const int iiw = w;
        float* fr = g_feats + (size_t)(b*NN + i0 + iiw)*1280 + 256;
#pragma unroll
        for (int h = 0; h < 8; ++h) {
            float il = 1.0f / l_s[iiw*8 + h];
            float* d = fr + h*128 + lane4;
            d[0] = aH[h].x*il; d[1] = aH[h].y*il;
            d[2] = aH[h].z*il; d[3] = aH[h].w*il;
        }
    } else {
#pragma unroll
        for (int ii = 0; ii < IT; ++ii) {
            float* fr = g_feats + (size_t)(b*NN + i0 + ii)*1280;
            fr[hs*16 + fs] = accs[ii] / l_s[ii*8 + hs];
            if (vp_act) pts_s[ii*96 + hp*12 + fp] = accp[ii] / l_s[ii*8 + hp];
        }
    }
    __syncthreads();
    if (tid < 96) {  // local-frame pts
        int hd = tid / 3, r = tid - hd*3;
#pragma unroll
        for (int ii = 0; ii < IT; ++ii) {
            float c0 = pts_s[ii*96 + hd*3 + 0] - T_s[ii*3 + 0];
            float c1 = pts_s[ii*96 + hd*3 + 1] - T_s[ii*3 + 1];
            float c2 = pts_s[ii*96 + hd*3 + 2] - T_s[ii*3 + 2];
            float loc = c0*R_s[ii*9 + r*3 + 0] + c1*R_s[ii*9 + r*3 + 1] + c2*R_s[ii*9 + r*3 + 2];
            g_feats[(size_t)(b*NN + i0 + ii)*1280 + 128 + tid] = loc;
            ptl_s[ii*96 + tid] = loc;
        }
    }
    __syncthreads();
    if (tid < 128) {
        int ii = tid >> 5, hd = tid & 31;
        float x = ptl_s[ii*96 + hd*3], y = ptl_s[ii*96 + hd*3 + 1], z = ptl_s[ii*96 + hd*3 + 2];
        g_feats[(size_t)(b*NN + i0 + ii)*1280 + 224 + hd] = sqrtf(x*x + y*y + z*z + EPSV);
    }
}

// ---------------- launcher ----------------
extern "C" void kernel_launch(void* const* d_in, const int* in_sizes, int n_in,
                              void* d_out, int out_size)
{
    const float* q_single  = (const float*)d_in[0];
    const float* kv_single = (const float*)d_in[1];
    const float* pairwise  = (const float*)d_in[2];
    const float* rot       = (const float*)d_in[3];
    const float* trans     = (const float*)d_in[4];
    const float* w_sq   = (const float*)d_in[7];
    const float* w_sk   = (const float*)d_in[8];
    const float* w_sv   = (const float*)d_in[9];
    const float* w_pq   = (const float*)d_in[10];
    const float* w_pk   = (const float*)d_in[11];
    const float* w_pv   = (const float*)d_in[12];
    const float* w_pair = (const float*)d_in[13];
    const float* b_pair = (const float*)d_in[14];
    const float* pw     = (const float*)d_in[15];
    const float* w_out  = (const float*)d_in[16];
    const float* b_out  = (const float*)d_in[17];
    float* out = (float*)d_out;

    float *p_q, *p_kv, *p_feats, *p_part, *p_bias;
    cudaGetSymbolAddress((void**)&p_q,  g_q);
    cudaGetSymbolAddress((void**)&p_kv, g_kv);
    cudaGetSymbolAddress((void**)&p_feats, g_feats);
    cudaGetSymbolAddress((void**)&p_part, g_part);
    cudaGetSymbolAddress((void**)&p_bias, g_bias);

    static int smem_set = 0;
    if (!smem_set) {
        cudaFuncSetAttribute(ipa_attn_kernel,
                             cudaFuncAttributeMaxDynamicSharedMemorySize, SM_BYTES);
        smem_set = 1;
    }

    // pair bias (DRAM-bound, independent of projections)
    pair_bias_kernel<<<TOK*NN/128, 256>>>(pairwise, w_pair, b_pair, p_bias);

    proj_fused_kernel<<<dim3(21, 16), 256>>>(
        q_single, kv_single, w_sq, w_pq, w_sk, w_sv, w_pk, w_pv, p_q, p_kv);

    rotate_q_kernel<<<TOK, 32>>>(rot, trans);
    rotate_kv_kernel<<<TOK, 32>>>(rot, trans);

    ipa_attn_kernel<<<BB*(NN/IT), 256, SM_BYTES>>>(pairwise, rot, trans, pw);

    out_gemm_part<<<dim3(6, 16, KSPLIT), 256>>>(p_feats, w_out, p_part);
    add_bias_kernel<<<TOK*DIMV/256, 256>>>(b_out, out);
}

// round 17
// speedup vs baseline: 1.4885x; 1.4885x over previous
#include <cuda_runtime.h>
#include <math.h>
#include <stdint.h>

// Problem constants (fixed shapes)
#define BB   2
#define NN   512
#define DIMV 384
#define TOK  (BB*NN)          // 1024

#define SCALAR_SCALE 0.14433756729740643f   // (3*16)^-0.5
#define POINT_SCALE  0.13608276348795434f   // (3*4*4.5)^-0.5
#define PAIR_SCALE   0.57735026918962576f   // 3^-0.5
#define EPSV 1e-8f

// attention tiling
#define IT 4      // queries per block
#define JT 32     // keys per tile

#define KSPLIT 4

// ---------------- device scratch ----------------
__device__ float g_q[TOK*224];
__device__ float g_kv[TOK*448];
__device__ float g_qsq[TOK*8];
__device__ float g_ksq[TOK*8];
__device__ float g_feats[TOK*1280];
__device__ float g_part[KSPLIT*TOK*DIMV];

// ---------------- cp.async helper ----------------
__device__ __forceinline__ void cp_async16(uint32_t smem_addr, const void* gptr) {
    asm volatile("cp.async.cg.shared.global [%0], [%1], 16;"
                 :: "r"(smem_addr), "l"(gptr));
}

// =====================================================================
// Fused projection GEMM: all 6 projections in one launch.
// =====================================================================
__global__ __launch_bounds__(256) void proj_fused_kernel(
    const float* __restrict__ q_in, const float* __restrict__ kv_in,
    const float* __restrict__ w_sq, const float* __restrict__ w_pq,
    const float* __restrict__ w_sk, const float* __restrict__ w_sv,
    const float* __restrict__ w_pk, const float* __restrict__ w_pv,
    float* __restrict__ Cq, float* __restrict__ Ckv)
{
    __shared__ __align__(16) float As[16][68];
    __shared__ __align__(16) float Ws[16][32];

    const int tid  = threadIdx.x;
    const int row0 = blockIdx.y * 64;
    const int col0 = blockIdx.x * 32;

    const float* A; const float* W; int nseg, wcol;
    float* C; int Ctot, ccol;
    if (col0 < 128)      { A=q_in;  W=w_sq; nseg=128; wcol=col0;     C=Cq;  Ctot=224; ccol=col0; }
    else if (col0 < 224) { A=q_in;  W=w_pq; nseg=96;  wcol=col0-128; C=Cq;  Ctot=224; ccol=col0; }
    else if (col0 < 352) { A=kv_in; W=w_sk; nseg=128; wcol=col0-224; C=Ckv; Ctot=448; ccol=col0-224; }
    else if (col0 < 480) { A=kv_in; W=w_sv; nseg=128; wcol=col0-352; C=Ckv; Ctot=448; ccol=col0-224; }
    else if (col0 < 576) { A=kv_in; W=w_pk; nseg=96;  wcol=col0-480; C=Ckv; Ctot=448; ccol=col0-224; }
    else                 { A=kv_in; W=w_pv; nseg=96;  wcol=col0-576; C=Ckv; Ctot=448; ccol=col0-224; }

    const int my = tid >> 4;
    const int nx = tid & 15;

    float acc[4][2];
#pragma unroll
    for (int i = 0; i < 4; ++i) { acc[i][0] = 0.f; acc[i][1] = 0.f; }

    const int lr = tid >> 2;
    const int lk = (tid & 3) * 4;

    for (int k0 = 0; k0 < DIMV; k0 += 16) {
        float4 av = *(const float4*)(A + (size_t)(row0 + lr)*DIMV + k0 + lk);
        As[lk+0][lr] = av.x; As[lk+1][lr] = av.y;
        As[lk+2][lr] = av.z; As[lk+3][lr] = av.w;
        if (tid < 128) {
            int wk = tid >> 3, wn = (tid & 7) * 4;
            *(float4*)&Ws[wk][wn] = *(const float4*)(W + (size_t)(k0 + wk)*nseg + wcol + wn);
        }
        __syncthreads();
#pragma unroll
        for (int kk = 0; kk < 16; ++kk) {
            float4 a = *(const float4*)&As[kk][my*4];
            float2 w = *(const float2*)&Ws[kk][nx*2];
            acc[0][0] += a.x*w.x; acc[0][1] += a.x*w.y;
            acc[1][0] += a.y*w.x; acc[1][1] += a.y*w.y;
            acc[2][0] += a.z*w.x; acc[2][1] += a.z*w.y;
            acc[3][0] += a.w*w.x; acc[3][1] += a.w*w.y;
        }
        __syncthreads();
    }
#pragma unroll
    for (int i = 0; i < 4; ++i) {
        float* cr = C + (size_t)(row0 + my*4 + i)*Ctot + ccol + nx*2;
        cr[0] = acc[i][0]; cr[1] = acc[i][1];
    }
}

// =====================================================================
// Output GEMM, 64x64 tile, 4x4 per thread, K split in 4 via blockIdx.z.
// =====================================================================
__global__ __launch_bounds__(256) void out_gemm_part(
    const float* __restrict__ A, const float* __restrict__ W,
    float* __restrict__ P)
{
    __shared__ __align__(16) float As[16][68];
    __shared__ __align__(16) float Ws[16][68];

    const int tid  = threadIdx.x;
    const int row0 = blockIdx.y * 64;
    const int col0 = blockIdx.x * 64;
    const int kh   = blockIdx.z;
    const int my = tid >> 4;
    const int nx = tid & 15;

    float acc[4][4];
#pragma unroll
    for (int i = 0; i < 4; ++i)
#pragma unroll
        for (int j = 0; j < 4; ++j) acc[i][j] = 0.f;

    const int lr = tid >> 2;
    const int lk = (tid & 3) * 4;
    const int wk = tid >> 4;
    const int wn = (tid & 15) * 4;

    const int kbeg = kh * 320, kend = kbeg + 320;

    for (int k0 = kbeg; k0 < kend; k0 += 16) {
        float4 av = *(const float4*)(A + (size_t)(row0 + lr)*1280 + k0 + lk);
        As[lk+0][lr] = av.x; As[lk+1][lr] = av.y;
        As[lk+2][lr] = av.z; As[lk+3][lr] = av.w;
        *(float4*)&Ws[wk][wn] = *(const float4*)(W + (size_t)(k0 + wk)*DIMV + col0 + wn);
        __syncthreads();
#pragma unroll
        for (int kk = 0; kk < 16; ++kk) {
            float4 a = *(const float4*)&As[kk][my*4];
            float4 w = *(const float4*)&Ws[kk][nx*4];
            acc[0][0] += a.x*w.x; acc[0][1] += a.x*w.y; acc[0][2] += a.x*w.z; acc[0][3] += a.x*w.w;
            acc[1][0] += a.y*w.x; acc[1][1] += a.y*w.y; acc[1][2] += a.y*w.z; acc[1][3] += a.y*w.w;
            acc[2][0] += a.z*w.x; acc[2][1] += a.z*w.y; acc[2][2] += a.z*w.z; acc[2][3] += a.z*w.w;
            acc[3][0] += a.w*w.x; acc[3][1] += a.w*w.y; acc[3][2] += a.w*w.z; acc[3][3] += a.w*w.w;
        }
        __syncthreads();
    }
    float* dst = P + (size_t)kh*TOK*DIMV;
#pragma unroll
    for (int i = 0; i < 4; ++i) {
        float* cr = dst + (size_t)(row0 + my*4 + i)*DIMV + col0 + nx*4;
        cr[0] = acc[i][0]; cr[1] = acc[i][1]; cr[2] = acc[i][2]; cr[3] = acc[i][3];
    }
}

__global__ __launch_bounds__(256) void add_bias_kernel(
    const float* __restrict__ bias, float* __restrict__ out)
{
    int idx = blockIdx.x * 256 + threadIdx.x;
    const int S = TOK*DIMV;
    float r = bias[idx % DIMV];
#pragma unroll
    for (int k = 0; k < KSPLIT; ++k) r += g_part[(size_t)k*S + idx];
    out[idx] = r;
}

// ---------------- rotate kernels ----------------
__global__ void rotate_q_kernel(const float* __restrict__ rot,
                                const float* __restrict__ trans)
{
    const int bn  = blockIdx.x;
    const int tid = threadIdx.x;   // 32
    float r[9], t3[3];
#pragma unroll
    for (int k = 0; k < 9; ++k) r[k] = rot[bn*9 + k];
#pragma unroll
    for (int k = 0; k < 3; ++k) t3[k] = trans[bn*3 + k];
    float* base = g_q + (size_t)bn*224 + 128 + tid*3;
    float c0 = base[0], c1 = base[1], c2 = base[2];
    float o0 = c0*r[0] + c1*r[3] + c2*r[6] + t3[0];
    float o1 = c0*r[1] + c1*r[4] + c2*r[7] + t3[1];
    float o2 = c0*r[2] + c1*r[5] + c2*r[8] + t3[2];
    base[0] = o0; base[1] = o1; base[2] = o2;
    float sq = o0*o0 + o1*o1 + o2*o2;
#pragma unroll
    for (int off = 1; off < 4; off <<= 1)
        sq += __shfl_xor_sync(0xffffffffu, sq, off);
    if ((tid & 3) == 0) g_qsq[bn*8 + (tid >> 2)] = sq;
}

__global__ void rotate_kv_kernel(const float* __restrict__ rot,
                                 const float* __restrict__ trans)
{
    const int bn  = blockIdx.x;
    const int tid = threadIdx.x;   // 32
    float r[9], t3[3];
#pragma unroll
    for (int k = 0; k < 9; ++k) r[k] = rot[bn*9 + k];
#pragma unroll
    for (int k = 0; k < 3; ++k) t3[k] = trans[bn*3 + k];
    float* arrs[2] = { g_kv + (size_t)bn*448 + 256,    // kp
                       g_kv + (size_t)bn*448 + 352 };  // vp
    float sq = 0.f;
#pragma unroll
    for (int a = 0; a < 2; ++a) {
        float* base = arrs[a] + tid*3;
        float c0 = base[0], c1 = base[1], c2 = base[2];
        float o0 = c0*r[0] + c1*r[3] + c2*r[6] + t3[0];
        float o1 = c0*r[1] + c1*r[4] + c2*r[7] + t3[1];
        float o2 = c0*r[2] + c1*r[5] + c2*r[8] + t3[2];
        base[0] = o0; base[1] = o1; base[2] = o2;
        if (a == 0) sq = o0*o0 + o1*o1 + o2*o2;
    }
#pragma unroll
    for (int off = 1; off < 4; off <<= 1)
        sq += __shfl_xor_sync(0xffffffffu, sq, off);
    if ((tid & 3) == 0) g_ksq[bn*8 + (tid >> 2)] = sq;
}

// =====================================================================
// Fused attention (R15 + cp.async tile loader).
// grid = 256, 256 threads, 2 blocks/SM forced.
// =====================================================================
// smem float offsets
#define OF_PAIR  0                      // 128 rows x 128 (swizzled)
#define OF_WEXP  16384                  // [ii][h][jj] 4*8*32
#define OF_PBIAS 17408                  // [h][row]    8*128 (transposed)
#define OF_WPM   18432                  // [p][h]      128*8 (pre-scaled)
#define OF_QS    19456                  // [ii][128]
#define OF_QP    19968                  // [ii][96]
#define OF_QSQ   20352                  // [ii][8]
#define OF_M     20384                  // [ii][8]
#define OF_L     20416
#define OF_ALPHA 20448
#define OF_COEF  20480                  // [8]
#define OF_BP    20488                  // [8]
#define OF_R     20496                  // [ii][9]
#define OF_T     20532                  // [ii][3]
#define OF_PTS   20544                  // [ii][96]
#define OF_PTSL  20928                  // [ii][96]
#define SM_FLOATS 21312
#define SM_BYTES (SM_FLOATS*4)

__global__ __launch_bounds__(256, 2) void ipa_attn_kernel(
    const float* __restrict__ pairwise,
    const float* __restrict__ rot,
    const float* __restrict__ trans,
    const float* __restrict__ w_pair,
    const float* __restrict__ b_pair,
    const float* __restrict__ point_w)
{
    extern __shared__ __align__(16) float sm[];
    float* pairT = sm + OF_PAIR;
    float* wexp  = sm + OF_WEXP;
    float* pbias = sm + OF_PBIAS;
    float* wpm   = sm + OF_WPM;
    float* qs_s  = sm + OF_QS;
    float* qp_s  = sm + OF_QP;
    float* qsq_s = sm + OF_QSQ;
    float* m_s   = sm + OF_M;
    float* l_s   = sm + OF_L;
    float* al_s  = sm + OF_ALPHA;
    float* cf_s  = sm + OF_COEF;
    float* bp_s  = sm + OF_BP;
    float* R_s   = sm + OF_R;
    float* T_s   = sm + OF_T;
    float* pts_s = sm + OF_PTS;
    float* ptl_s = sm + OF_PTSL;

    const int tid  = threadIdx.x;
    const int bid  = blockIdx.x;
    const int b    = bid >> 7;
    const int i0   = (bid & 127) * IT;
    const int w    = tid >> 5;
    const int lane = tid & 31;

    const uint32_t pair_u32 = (uint32_t)__cvta_generic_to_shared(pairT);

    // ---- prologue loads ----
#pragma unroll
    for (int l = 0; l < 2; ++l) {             // qs: 512 floats
        int idx = l*256 + tid;
        int ii = idx >> 7;
        qs_s[idx] = g_q[(size_t)(b*NN + i0 + ii)*224 + (idx & 127)];
    }
#pragma unroll
    for (int idx = tid; idx < IT*96; idx += 256) {   // qp: 384 floats
        int ii = idx / 96;
        qp_s[idx] = g_q[(size_t)(b*NN + i0 + ii)*224 + 128 + (idx % 96)];
    }
    if (tid < 32) {
        int ii = tid >> 3;
        qsq_s[tid] = g_qsq[(size_t)(b*NN + i0 + ii)*8 + (tid & 7)];
        m_s[tid] = -1e30f;
        l_s[tid] = 0.f;
    }
    if (tid < 8) {
        bp_s[tid] = b_pair[tid] * PAIR_SCALE;
        float x = point_w[tid];
        cf_s[tid] = -0.5f * POINT_SCALE * log1pf(__expf(x));
    }
#pragma unroll
    for (int l = 0; l < 4; ++l) wpm[l*256 + tid] = w_pair[l*256 + tid] * PAIR_SCALE;
    if (tid >= 64 && tid < 100) {             // R: 36
        int idx = tid - 64;
        int ii = idx / 9;
        R_s[idx] = rot[(size_t)(b*NN + i0 + ii)*9 + (idx % 9)];
    }
    if (tid >= 100 && tid < 112) {            // T: 12
        int idx = tid - 100;
        int ii = idx / 3;
        T_s[idx] = trans[(size_t)(b*NN + i0 + ii)*3 + (idx % 3)];
    }
    __syncthreads();

    // persistent accumulators
    float4 aH[8];                             // res_pair (warps 0-3): warp=ii, 8 heads
#pragma unroll
    for (int h = 0; h < 8; ++h) aH[h] = make_float4(0,0,0,0);
    float accs[IT] = {0,0,0,0}, accp[IT] = {0,0,0,0};   // value (warps 4-7)
    const int tv = tid - 128;
    const int hs = (tv >= 0) ? (tv >> 4) : 0;
    const int fs = (tv >= 0) ? (tv & 15) : 0;
    const bool vp_act = (tv >= 0) && (tv < 96);
    const int hp = vp_act ? (tv / 12) : 0;
    const int fp = vp_act ? (tv % 12) : 0;

    const float* gp_base = pairwise + ((size_t)b*NN + i0) * NN * 128;
    const int lane4 = lane << 2;

    for (int tile = 0; tile < 16; ++tile) {
        const int j0 = tile * JT;
        // ---- load pair tiles via cp.async: 4 ii x 32 jj x 128 p (swizzled) ----
        {
#pragma unroll
            for (int l = 0; l < 16; ++l) {
                int idx = l*256 + tid;
                int ii  = idx >> 10;
                int rem = idx & 1023;
                int jj  = rem >> 5;
                int q   = rem & 31;
                int physq = q ^ (jj & 7);
                uint32_t dst = pair_u32 + ((((unsigned)(ii*JT + jj) << 7) + ((unsigned)physq << 2)) << 2);
                cp_async16(dst, gp_base + ((size_t)ii*NN + j0 + jj)*128 + (q << 2));
            }
            asm volatile("cp.async.commit_group;");
            asm volatile("cp.async.wait_group 0;");
        }
        __syncthreads();

        // ---- phase A ----
        if (tid < 128) {
            // bias: row = (ii,jj), all 8 heads, full p; swizzled conflict-free
            const int row = tid;
            const float* prow = &pairT[row << 7];
            const int rk = row & 7;
            float acc[8];
#pragma unroll
            for (int h = 0; h < 8; ++h) acc[h] = 0.f;
#pragma unroll 8
            for (int i = 0; i < 32; ++i) {
                float4 pv = *(const float4*)(prow + ((i ^ rk) << 2));
                const float* wp = &wpm[i*32];
                float pe[4] = { pv.x, pv.y, pv.z, pv.w };
#pragma unroll
                for (int e = 0; e < 4; ++e) {
                    float4 wa = *(const float4*)(wp + e*8);
                    float4 wb = *(const float4*)(wp + e*8 + 4);
                    acc[0] += pe[e]*wa.x; acc[1] += pe[e]*wa.y;
                    acc[2] += pe[e]*wa.z; acc[3] += pe[e]*wa.w;
                    acc[4] += pe[e]*wb.x; acc[5] += pe[e]*wb.y;
                    acc[6] += pe[e]*wb.z; acc[7] += pe[e]*wb.w;
                }
            }
#pragma unroll
            for (int h = 0; h < 8; ++h) pbias[h*128 + row] = acc[h];
        } else {
            // z-base: t -> (jj, head-quad), 2 heads, 4 ii each
            const int t  = tid - 128;
            const int jj = t >> 2;
            const int q4 = t & 3;
            const size_t bj = (size_t)b*NN + j0 + jj;
            const float* kvr = g_kv + bj*448;
            const float* kqp = g_ksq + bj*8;
#pragma unroll
            for (int hh = 0; hh < 2; ++hh) {
                const int h = q4 + hh*4;
                float4 kf0 = *(const float4*)(kvr + h*16);
                float4 kf1 = *(const float4*)(kvr + h*16 + 4);
                float4 kf2 = *(const float4*)(kvr + h*16 + 8);
                float4 kf3 = *(const float4*)(kvr + h*16 + 12);
                float4 kp0 = *(const float4*)(kvr + 256 + h*12);
                float4 kp1 = *(const float4*)(kvr + 256 + h*12 + 4);
                float4 kp2 = *(const float4*)(kvr + 256 + h*12 + 8);
                float kq = kqp[h];
                float bz = bp_s[h];
                float cf = cf_s[h];
#pragma unroll
                for (int ii = 0; ii < IT; ++ii) {
                    const float* qsr = qs_s + ii*128 + h*16;
                    const float* qpr = qp_s + ii*96 + h*12;
                    float4 q0 = *(const float4*)(qsr);
                    float4 q1 = *(const float4*)(qsr + 4);
                    float4 q2 = *(const float4*)(qsr + 8);
                    float4 q3 = *(const float4*)(qsr + 12);
                    float s = q0.x*kf0.x + q0.y*kf0.y + q0.z*kf0.z + q0.w*kf0.w
                            + q1.x*kf1.x + q1.y*kf1.y + q1.z*kf1.z + q1.w*kf1.w
                            + q2.x*kf2.x + q2.y*kf2.y + q2.z*kf2.z + q2.w*kf2.w
                            + q3.x*kf3.x + q3.y*kf3.y + q3.z*kf3.z + q3.w*kf3.w;
                    float4 p0 = *(const float4*)(qpr);
                    float4 p1 = *(const float4*)(qpr + 4);
                    float4 p2 = *(const float4*)(qpr + 8);
                    float dt = p0.x*kp0.x + p0.y*kp0.y + p0.z*kp0.z + p0.w*kp0.w
                             + p1.x*kp1.x + p1.y*kp1.y + p1.z*kp1.z + p1.w*kp1.w
                             + p2.x*kp2.x + p2.y*kp2.y + p2.z*kp2.z + p2.w*kp2.w;
                    float dist = qsq_s[ii*8 + h] + kq - 2.f*dt;
                    wexp[ii*256 + h*32 + jj] = s*SCALAR_SCALE + bz + cf*dist;
                }
            }
        }
        __syncthreads();

        // ---- phase C: bias fold + online softmax (warp w owns head w) ----
        {
#pragma unroll
            for (int ii = 0; ii < IT; ++ii) {
                float v = wexp[ii*256 + w*32 + lane] + pbias[w*128 + ii*JT + lane];
                float mx = v;
#pragma unroll
                for (int off = 16; off; off >>= 1)
                    mx = fmaxf(mx, __shfl_xor_sync(0xffffffffu, mx, off));
                float mold = m_s[ii*8 + w];
                float mnew = fmaxf(mold, mx);
                float a = __expf(mold - mnew);
                float e = __expf(v - mnew);
                wexp[ii*256 + w*32 + lane] = e;
                float smv = e;
#pragma unroll
                for (int off = 16; off; off >>= 1)
                    smv += __shfl_xor_sync(0xffffffffu, smv, off);
                if (lane == 0) {
                    l_s[ii*8 + w] = l_s[ii*8 + w]*a + smv;
                    m_s[ii*8 + w] = mnew;
                    al_s[ii*8 + w] = a;
                }
            }
        }
        __syncthreads();

        // ---- phase D ----
        if (tid < 128) {
            // res_pair: warp w owns QUERY ii=w, all 8 heads; lane owns p-quad.
            const int iiw = w;
#pragma unroll
            for (int h = 0; h < 8; ++h) {
                float sA = al_s[iiw*8 + h];
                aH[h].x *= sA; aH[h].y *= sA; aH[h].z *= sA; aH[h].w *= sA;
            }
            const float* we = &wexp[iiw*256];
            const float* tb = &pairT[(iiw*JT) << 7];
#pragma unroll
            for (int jj = 0; jj < JT; jj += 4) {
                float4 r0 = *(const float4*)(tb + ((jj+0)<<7) + (lane4 ^ (((jj+0)&7)<<2)));
                float4 r1 = *(const float4*)(tb + ((jj+1)<<7) + (lane4 ^ (((jj+1)&7)<<2)));
                float4 r2 = *(const float4*)(tb + ((jj+2)<<7) + (lane4 ^ (((jj+2)&7)<<2)));
                float4 r3 = *(const float4*)(tb + ((jj+3)<<7) + (lane4 ^ (((jj+3)&7)<<2)));
#pragma unroll
                for (int h = 0; h < 8; ++h) {
                    float4 wA = *(const float4*)(we + h*32 + jj);   // broadcast
                    aH[h].x += wA.x*r0.x + wA.y*r1.x + wA.z*r2.x + wA.w*r3.x;
                    aH[h].y += wA.x*r0.y + wA.y*r1.y + wA.z*r2.y + wA.w*r3.y;
                    aH[h].z += wA.x*r0.z + wA.y*r1.z + wA.z*r2.z + wA.w*r3.z;
                    aH[h].w += wA.x*r0.w + wA.y*r1.w + wA.z*r2.w + wA.w*r3.w;
                }
            }
        } else {
            // values: scalar feats (all 128) + point feats (first 96)
#pragma unroll
            for (int ii = 0; ii < IT; ++ii) {
                accs[ii] *= al_s[ii*8 + hs];
                if (vp_act) accp[ii] *= al_s[ii*8 + hp];
            }
            const float* vbase = g_kv + ((size_t)b*NN + j0)*448;
            const float* svs = vbase + 128 + hs*16 + fs;
            const float* svp = vbase + 352 + hp*12 + fp;
#pragma unroll
            for (int jj4 = 0; jj4 < JT; jj4 += 4) {
                float v0 = svs[(size_t)(jj4+0)*448];
                float v1 = svs[(size_t)(jj4+1)*448];
                float v2 = svs[(size_t)(jj4+2)*448];
                float v3 = svs[(size_t)(jj4+3)*448];
#pragma unroll
                for (int ii = 0; ii < IT; ++ii) {
                    float4 w4 = *(const float4*)&wexp[ii*256 + hs*32 + jj4];
                    accs[ii] += w4.x*v0 + w4.y*v1 + w4.z*v2 + w4.w*v3;
                }
                if (vp_act) {
                    float u0 = svp[(size_t)(jj4+0)*448];
                    float u1 = svp[(size_t)(jj4+1)*448];
                    float u2 = svp[(size_t)(jj4+2)*448];
                    float u3 = svp[(size_t)(jj4+3)*448];
#pragma unroll
                    for (int ii = 0; ii < IT; ++ii) {
                        float4 w4 = *(const float4*)&wexp[ii*256 + hp*32 + jj4];
                        accp[ii] += w4.x*u0 + w4.y*u1 + w4.z*u2 + w4.w*u3;
                    }
                }
            }
        }
        __syncthreads();
    }

    // ---- finalize ----
    if (tid < 128) {
        const int iiw = w;
        float* fr = g_feats + (size_t)(b*NN + i0 + iiw)*1280 + 256;
#pragma unroll
        for (int h = 0; h < 8; ++h) {
            float il = 1.0f / l_s[iiw*8 + h];
            float* d = fr + h*128 + lane4;
            d[0] = aH[h].x*il; d[1] = aH[h].y*il;
            d[2] = aH[h].z*il; d[3] = aH[h].w*il;
        }
    } else {
#pragma unroll
        for (int ii = 0; ii < IT; ++ii) {
            float* fr = g_feats + (size_t)(b*NN + i0 + ii)*1280;
            fr[hs*16 + fs] = accs[ii] / l_s[ii*8 + hs];
            if (vp_act) pts_s[ii*96 + hp*12 + fp] = accp[ii] / l_s[ii*8 + hp];
        }
    }
    __syncthreads();
    if (tid < 96) {  // local-frame pts
        int hd = tid / 3, r = tid - hd*3;
#pragma unroll
        for (int ii = 0; ii < IT; ++ii) {
            float c0 = pts_s[ii*96 + hd*3 + 0] - T_s[ii*3 + 0];
            float c1 = pts_s[ii*96 + hd*3 + 1] - T_s[ii*3 + 1];
            float c2 = pts_s[ii*96 + hd*3 + 2] - T_s[ii*3 + 2];
            float loc = c0*R_s[ii*9 + r*3 + 0] + c1*R_s[ii*9 + r*3 + 1] + c2*R_s[ii*9 + r*3 + 2];
            g_feats[(size_t)(b*NN + i0 + ii)*1280 + 128 + tid] = loc;
            ptl_s[ii*96 + tid] = loc;
        }
    }
    __syncthreads();
    if (tid < 128) {
        int ii = tid >> 5, hd = tid & 31;
        float x = ptl_s[ii*96 + hd*3], y = ptl_s[ii*96 + hd*3 + 1], z = ptl_s[ii*96 + hd*3 + 2];
        g_feats[(size_t)(b*NN + i0 + ii)*1280 + 224 + hd] = sqrtf(x*x + y*y + z*z + EPSV);
    }
}

// ---------------- launcher ----------------
extern "C" void kernel_launch(void* const* d_in, const int* in_sizes, int n_in,
                              void* d_out, int out_size)
{
    const float* q_single  = (const float*)d_in[0];
    const float* kv_single = (const float*)d_in[1];
    const float* pairwise  = (const float*)d_in[2];
    const float* rot       = (const float*)d_in[3];
    const float* trans     = (const float*)d_in[4];
    const float* w_sq   = (const float*)d_in[7];
    const float* w_sk   = (const float*)d_in[8];
    const float* w_sv   = (const float*)d_in[9];
    const float* w_pq   = (const float*)d_in[10];
    const float* w_pk   = (const float*)d_in[11];
    const float* w_pv   = (const float*)d_in[12];
    const float* w_pair = (const float*)d_in[13];
    const float* b_pair = (const float*)d_in[14];
    const float* pw     = (const float*)d_in[15];
    const float* w_out  = (const float*)d_in[16];
    const float* b_out  = (const float*)d_in[17];
    float* out = (float*)d_out;

    float *p_q, *p_kv, *p_feats, *p_part;
    cudaGetSymbolAddress((void**)&p_q,  g_q);
    cudaGetSymbolAddress((void**)&p_kv, g_kv);
    cudaGetSymbolAddress((void**)&p_feats, g_feats);
    cudaGetSymbolAddress((void**)&p_part, g_part);

    static int smem_set = 0;
    if (!smem_set) {
        cudaFuncSetAttribute(ipa_attn_kernel,
                             cudaFuncAttributeMaxDynamicSharedMemorySize, SM_BYTES);
        smem_set = 1;
    }

    proj_fused_kernel<<<dim3(21, 16), 256>>>(
        q_single, kv_single, w_sq, w_pq, w_sk, w_sv, w_pk, w_pv, p_q, p_kv);

    rotate_q_kernel<<<TOK, 32>>>(rot, trans);
    rotate_kv_kernel<<<TOK, 32>>>(rot, trans);

    ipa_attn_kernel<<<BB*(NN/IT), 256, SM_BYTES>>>(pairwise, rot, trans, w_pair, b_pair, pw);

    out_gemm_part<<<dim3(6, 16, KSPLIT), 256>>>(p_feats, w_out, p_part);
    add_bias_kernel<<<TOK*DIMV/256, 256>>>(b_out, out);
}